// round 14
// baseline (speedup 1.0000x reference)
#include <cuda_runtime.h>
#include <cuda_bf16.h>

#define R_MAX 2.0f
#define DR_MIN 0.02f
#define PI_F 3.14159265358979f
#define NBLOCKS 148
#define NTHREADS 768

__device__ unsigned char g_Z8[204800];
__device__ float g_partials[NBLOCKS];
__device__ unsigned int g_count = 0;

__global__ void z_to_u8_kernel(const int* __restrict__ Z, int n)
{
    int i = blockIdx.x * blockDim.x + threadIdx.x;
    int n4 = n >> 2;
    if (i < n4) {
        int4 z = __ldg((const int4*)Z + i);
        ((uchar4*)g_Z8)[i] = make_uchar4((unsigned char)z.x, (unsigned char)z.y,
                                         (unsigned char)z.z, (unsigned char)z.w);
    }
    if (i == 0) {
        for (int k = n4 << 2; k < n; k++) g_Z8[k] = (unsigned char)Z[k];
    }
}

__device__ __forceinline__ float4 shfl_f4(float4 v, int src) {
    float4 r;
    r.x = __shfl_sync(0xFFFFFFFF, v.x, src);
    r.y = __shfl_sync(0xFFFFFFFF, v.y, src);
    r.z = __shfl_sync(0xFFFFFFFF, v.z, src);
    r.w = __shfl_sync(0xFFFFFFFF, v.w, src);
    return r;
}

// 8 replicated tables, stride 129 float2 (1032B => +2 bank shift per copy)
#define TAB_STRIDE 129
#define TAB_BYTES 8256   // 8*129*8

__global__ void __launch_bounds__(NTHREADS, 1)
exp_rep_kernel(const float* __restrict__ dr_vec,
               const int* __restrict__ idx_i,
               const int* __restrict__ idx_j,
               const float* __restrict__ rep_scale,
               const float* __restrict__ rep_prefactor,
               float* __restrict__ out,
               int n_edges, int n_atoms)
{
    extern __shared__ unsigned char smem[];
    float2* s_tab = (float2*)smem;                 // 8 copies
    unsigned char* s_Z = smem + TAB_BYTES;         // n_atoms bytes

    int tid = threadIdx.x;
    int lane = tid & 31;
    if (tid < 119) {
        float2 v = make_float2(fabsf(rep_prefactor[tid]),
                               1.0f / fabsf(rep_scale[tid]));
        #pragma unroll
        for (int cp = 0; cp < 8; cp++)
            s_tab[cp * TAB_STRIDE + tid] = v;
    }
    // stage u8 Z -> smem (16B chunks)
    int n16 = n_atoms >> 4;
    const int4* gZ16 = (const int4*)g_Z8;
    int4* sZ16 = (int4*)s_Z;
    for (int i = tid; i < n16; i += NTHREADS)
        sZ16[i] = __ldg(gZ16 + i);
    for (int i = (n16 << 4) + tid; i < n_atoms; i += NTHREADS)
        s_Z[i] = g_Z8[i];
    __syncthreads();

    const float2* my_tab = s_tab + (lane & 7) * TAB_STRIDE;

    // shuffle-transpose selectors (loop-invariant):
    // round w: lane L needs float4 #(3L+w) -> source lane (3L+w)&31;
    // source lane S exposes register floor(k/32), k = 3*((S-w)*11 mod 32) + w
    int sl0 = (3 * lane + 0) & 31;
    int sl1 = (3 * lane + 1) & 31;
    int sl2 = (3 * lane + 2) & 31;
    int rs0 = (3 * (((lane - 0) * 11) & 31) + 0) >> 5;
    int rs1 = (3 * (((lane - 1) * 11) & 31) + 1) >> 5;
    int rs2 = (3 * (((lane - 2) * 11) & 31) + 2) >> 5;

    float acc0 = 0.0f, acc1 = 0.0f;
    int m = n_edges >> 2;
    int s = NBLOCKS * NTHREADS;
    const float4* dv4 = (const float4*)dr_vec;
    const int4*   I4  = (const int4*)idx_i;
    const int4*   J4  = (const int4*)idx_j;

    // ---- pipeline: idx depth-2, coalesced dv depth-1, L2 hints depth-3 ----
    int c0 = blockIdx.x * NTHREADS + tid;        // (c0 & 31) == lane
    bool w0 = (c0 & ~31) < m;                     // warp-uniform
    bool l0 = c0 < m;
    bool fast0 = (c0 | 31) < m;
    float4 A = make_float4(0.f,0.f,0.f,0.f), B = A, C = A;
    int4 ii0 = make_int4(0,0,0,0), jj0 = ii0, ii1 = ii0, jj1 = ii0;
    if (w0) {
        if (fast0) {
            int fb = 3 * (c0 & ~31);
            A = __ldcs(dv4 + fb + lane);
            B = __ldcs(dv4 + fb + 32 + lane);
            C = __ldcs(dv4 + fb + 64 + lane);
        } else if (l0) {
            A = __ldcs(dv4 + 3 * c0 + 0);
            B = __ldcs(dv4 + 3 * c0 + 1);
            C = __ldcs(dv4 + 3 * c0 + 2);
        }
        if (l0) {
            ii0 = __ldcs(I4 + c0);
            jj0 = __ldcs(J4 + c0);
        }
    }
    int c1 = c0 + s;
    bool l1 = c1 < m;
    if (l1) {
        ii1 = __ldcs(I4 + c1);
        jj1 = __ldcs(J4 + c1);
    }

    while (w0) {
        int c2 = c0 + 2 * s;
        int cpre = c0 + 3 * s;
        // L2 prefetch hints, 3 iterations ahead (fire-and-forget)
        if (cpre < m) {
            asm volatile("prefetch.global.L2 [%0];" :: "l"(dv4 + 3 * cpre) : "memory");
            asm volatile("prefetch.global.L2 [%0];" :: "l"(I4 + cpre) : "memory");
            asm volatile("prefetch.global.L2 [%0];" :: "l"(J4 + cpre) : "memory");
        }

        // prefetch dv for c1 (coalesced fast path)
        bool w1 = (c1 & ~31) < m;
        bool fast1 = (c1 | 31) < m;
        float4 nA = A, nB = B, nC = C;
        if (w1) {
            if (fast1) {
                int fb = 3 * (c1 & ~31);
                nA = __ldcs(dv4 + fb + lane);
                nB = __ldcs(dv4 + fb + 32 + lane);
                nC = __ldcs(dv4 + fb + 64 + lane);
            } else if (l1) {
                nA = __ldcs(dv4 + 3 * c1 + 0);
                nB = __ldcs(dv4 + 3 * c1 + 1);
                nC = __ldcs(dv4 + 3 * c1 + 2);
            }
        }
        // prefetch idx for c2
        bool l2 = c2 < m;
        int4 ii2 = ii1, jj2 = jj1;
        if (l2) {
            ii2 = __ldcs(I4 + c2);
            jj2 = __ldcs(J4 + c2);
        }

        // ---- compute chunk c0 ----
        float4 va, vb, vc;
        if (fast0) {
            float4 e0 = (rs0 == 0) ? A : ((rs0 == 1) ? B : C);
            float4 e1 = (rs1 == 0) ? A : ((rs1 == 1) ? B : C);
            float4 e2 = (rs2 == 0) ? A : ((rs2 == 1) ? B : C);
            va = shfl_f4(e0, sl0);
            vb = shfl_f4(e1, sl1);
            vc = shfl_f4(e2, sl2);
        } else {
            va = A; vb = B; vc = C;
        }

        if (l0) {
            float ex[4], ey[4], ez[4];
            ex[0] = va.x; ey[0] = va.y; ez[0] = va.z;
            ex[1] = va.w; ey[1] = vb.x; ez[1] = vb.y;
            ex[2] = vb.z; ey[2] = vb.w; ez[2] = vc.x;
            ex[3] = vc.y; ey[3] = vc.z; ez[3] = vc.w;
            int ii[4] = {ii0.x, ii0.y, ii0.z, ii0.w};
            int jj[4] = {jj0.x, jj0.y, jj0.z, jj0.w};

            int zi[4], zj[4];
            #pragma unroll
            for (int k = 0; k < 4; k++) {
                zi[k] = (int)s_Z[ii[k]];
                zj[k] = (int)s_Z[jj[k]];
            }
            float2 pi[4], pj[4];
            #pragma unroll
            for (int k = 0; k < 4; k++) {
                pi[k] = my_tab[zi[k]];
                pj[k] = my_tab[zj[k]];
            }

            #pragma unroll
            for (int k = 0; k < 4; k++) {
                float r2 = fmaf(ex[k], ex[k], fmaf(ey[k], ey[k], ez[k] * ez[k]));
                float r2c = fmaxf(r2, DR_MIN * DR_MIN);
                float inv_r2 = __fdividef(1.0f, r2c);   // parallel to sqrt
                float dr = sqrtf(r2c);
                // reference clamps dr to [0.02, 2]; cos factor is 0 at
                // dr >= 2, so mask instead of clamping high.
                bool live = (dr < R_MAX) & (ii[k] != jj[k]);
                float cosc = 0.5f * (__cosf(dr * (PI_F / R_MAX)) + 1.0f);
                float e = __expf(-dr * (pi[k].y + pj[k].y));
                float f = pi[k].x * pj[k].x * e * cosc * inv_r2;
                if (k & 1) acc1 += live ? f : 0.0f;
                else       acc0 += live ? f : 0.0f;
            }
        }

        // rotate pipeline
        c0 = c1; w0 = w1; l0 = l1; fast0 = fast1;
        c1 = c2; l1 = l2;
        A = nA; B = nB; C = nC;
        ii0 = ii1; jj0 = jj1;
        ii1 = ii2; jj1 = jj2;
    }

    float acc = acc0 + acc1;

    // remainder edges (n_edges % 4): block 0, thread 0
    if (blockIdx.x == 0 && tid == 0) {
        for (int e = m << 2; e < n_edges; e++) {
            float dx = dr_vec[3*e+0], dy = dr_vec[3*e+1], dz = dr_vec[3*e+2];
            int ii = idx_i[e], jj = idx_j[e];
            float2 pi = my_tab[(int)s_Z[ii]];
            float2 pj = my_tab[(int)s_Z[jj]];
            float r2c = fmaxf(dx*dx + dy*dy + dz*dz, DR_MIN * DR_MIN);
            float dr = sqrtf(r2c);
            bool live = (dr < R_MAX) & (ii != jj);
            float cosc = 0.5f * (__cosf(dr * (PI_F / R_MAX)) + 1.0f);
            float f = pi.x * pj.x * __expf(-dr * (pi.y + pj.y)) * cosc *
                      __fdividef(1.0f, r2c);
            acc += live ? f : 0.0f;
        }
    }

    // warp reduce, block reduce, deterministic cross-block finish
    #pragma unroll
    for (int off = 16; off > 0; off >>= 1)
        acc += __shfl_down_sync(0xFFFFFFFF, acc, off);

    __shared__ float s_red[32];
    int warp = tid >> 5;
    if (lane == 0) s_red[warp] = acc;
    __syncthreads();
    if (warp == 0) {
        float v = (tid < (NTHREADS / 32)) ? s_red[tid] : 0.0f;
        #pragma unroll
        for (int off = 16; off > 0; off >>= 1)
            v += __shfl_down_sync(0xFFFFFFFF, v, off);
        if (tid == 0) {
            g_partials[blockIdx.x] = v;
            __threadfence();
            unsigned int ticket = atomicAdd(&g_count, 1u);
            if (ticket == NBLOCKS - 1) {
                float sum = 0.0f;
                #pragma unroll 4
                for (int i = 0; i < NBLOCKS; i++) sum += g_partials[i];
                out[0] = sum;
                g_count = 0;  // reset for next graph replay
            }
        }
    }
}

extern "C" void kernel_launch(void* const* d_in, const int* in_sizes, int n_in,
                              void* d_out, int out_size)
{
    const float* dr_vec        = (const float*)d_in[1];
    const int*   Z             = (const int*)d_in[2];
    const int*   idx           = (const int*)d_in[3];
    const float* rep_scale     = (const float*)d_in[6];
    const float* rep_prefactor = (const float*)d_in[7];
    float* out = (float*)d_out;

    int n_edges = in_sizes[1] / 3;
    int n_atoms = in_sizes[2];
    const int* idx_i = idx;
    const int* idx_j = idx + n_edges;

    int n4 = n_atoms >> 2;
    z_to_u8_kernel<<<(n4 + 255) / 256, 256>>>(Z, n_atoms);

    int smem_bytes = TAB_BYTES + ((n_atoms + 15) & ~15);
    cudaFuncSetAttribute(exp_rep_kernel,
                         cudaFuncAttributeMaxDynamicSharedMemorySize, smem_bytes);

    exp_rep_kernel<<<NBLOCKS, NTHREADS, smem_bytes>>>(
        dr_vec, idx_i, idx_j, rep_scale, rep_prefactor,
        out, n_edges, n_atoms);
}